// round 4
// baseline (speedup 1.0000x reference)
#include <cuda_runtime.h>

#define T_STEPS 100
#define BATCH   512
#define D0      700
#define D1      512
#define D2      20
#define M_TOT   (T_STEPS * BATCH)          // 51200

#define S2_ELEMS (T_STEPS * BATCH * D2)    // 1,024,000
#define S1_ELEMS (T_STEPS * BATCH * D1)    // 26,214,400

#define ALPHA 0.8f
#define BETA  0.9f
#define THR   1.0f

// Scratch (allocation-free rule: static __device__ globals)
__device__ float g_pre1[T_STEPS * BATCH * D1];   // 104.9 MB
__device__ float g_W1t[D0 * D1];                 // 1.4 MB, K-major -> [k][n]

// ---------------------------------------------------------------------------
// Kernel 0: transpose W1 [D1, D0] -> g_W1t [D0, D1] for coalesced GEMM loads
// ---------------------------------------------------------------------------
__global__ void k_transpose_w1(const float* __restrict__ W1) {
    int idx = blockIdx.x * blockDim.x + threadIdx.x;
    if (idx >= D0 * D1) return;
    int k = idx / D1;
    int n = idx - k * D1;
    g_W1t[idx] = W1[n * D0 + k];
}

// ---------------------------------------------------------------------------
// Kernel 1: SGEMM  C[m,n] = sum_k A[m,k] * W1t[k,n]
//   A = x  (M=51200 x K=700 row-major), C = g_pre1 (M x N=512)
//   128x128 block tile, BK=8, 8x8 per thread, 256 threads.
// ---------------------------------------------------------------------------
__global__ __launch_bounds__(256)
void k_sgemm(const float* __restrict__ A) {
    const int K = D0;
    const int N = D1;

    __shared__ float As[8][128];   // transposed A tile: As[k][m]
    __shared__ float Bs[8][128];   // Bs[k][n]

    const int bm  = blockIdx.y * 128;
    const int bn  = blockIdx.x * 128;
    const int tid = threadIdx.x;
    const int tx  = tid & 15;      // n-direction thread coord
    const int ty  = tid >> 4;      // m-direction thread coord

    // A-tile load mapping: 128 rows x 8 cols = 256 float4 (2 per row)
    const int a_row = tid >> 1;          // 0..127
    const int a_col = (tid & 1) << 2;    // 0 or 4
    // B-tile load mapping: 8 rows x 128 cols = 256 float4 (32 per row)
    const int b_row = tid >> 5;          // 0..7
    const int b_col = (tid & 31) << 2;   // 0..124

    const float* Ab = A + (size_t)(bm + a_row) * K + a_col;

    float acc[8][8] = {};

    for (int k0 = 0; k0 < K; k0 += 8) {
        // ---- load A tile (guard K remainder: K=700, last iter covers 696..703)
        float4 av;
        int ka = k0 + a_col;
        if (ka + 3 < K) {
            av = *reinterpret_cast<const float4*>(Ab + k0);
        } else {
            av.x = (ka + 0 < K) ? Ab[k0 + 0] : 0.0f;
            av.y = (ka + 1 < K) ? Ab[k0 + 1] : 0.0f;
            av.z = (ka + 2 < K) ? Ab[k0 + 2] : 0.0f;
            av.w = (ka + 3 < K) ? Ab[k0 + 3] : 0.0f;
        }
        As[a_col + 0][a_row] = av.x;
        As[a_col + 1][a_row] = av.y;
        As[a_col + 2][a_row] = av.z;
        As[a_col + 3][a_row] = av.w;

        // ---- load B tile
        int kb = k0 + b_row;
        float4 bv = make_float4(0.0f, 0.0f, 0.0f, 0.0f);
        if (kb < K) {
            bv = *reinterpret_cast<const float4*>(&g_W1t[(size_t)kb * N + bn + b_col]);
        }
        *reinterpret_cast<float4*>(&Bs[b_row][b_col]) = bv;

        __syncthreads();

        #pragma unroll
        for (int kk = 0; kk < 8; kk++) {
            float ra[8], rb[8];
            #pragma unroll
            for (int i = 0; i < 8; i++) ra[i] = As[kk][ty * 8 + i];
            #pragma unroll
            for (int j = 0; j < 8; j++) rb[j] = Bs[kk][tx * 8 + j];
            #pragma unroll
            for (int i = 0; i < 8; i++)
                #pragma unroll
                for (int j = 0; j < 8; j++)
                    acc[i][j] += ra[i] * rb[j];
        }
        __syncthreads();
    }

    // ---- store C (M,N both multiples of 128: no edge guards)
    float* Cb = g_pre1 + (size_t)(bm + ty * 8) * N + bn + tx * 8;
    #pragma unroll
    for (int i = 0; i < 8; i++) {
        *reinterpret_cast<float4*>(Cb + (size_t)i * N + 0) =
            make_float4(acc[i][0], acc[i][1], acc[i][2], acc[i][3]);
        *reinterpret_cast<float4*>(Cb + (size_t)i * N + 4) =
            make_float4(acc[i][4], acc[i][5], acc[i][6], acc[i][7]);
    }
}

// ---------------------------------------------------------------------------
// Kernel 2: layer-1 LIF scan. One thread per (b, o). Coalesced over o.
//   syn = a*syn + pre; reset = (mem_prev > THR); mem = (b*mem_prev+syn)*(1-reset);
//   spk = (mem - THR > 0)
// ---------------------------------------------------------------------------
__global__ void k_scan1(float* __restrict__ s1) {
    int idx = blockIdx.x * blockDim.x + threadIdx.x;   // b*D1 + o
    if (idx >= BATCH * D1) return;

    float syn = 0.0f, mem = 0.0f;
    const float* p = g_pre1 + idx;
    float* s = s1 + idx;

    #pragma unroll 4
    for (int t = 0; t < T_STEPS; t++) {
        float pr = p[(size_t)t * (BATCH * D1)];
        syn = ALPHA * syn + pr;
        float reset = (mem > THR) ? 1.0f : 0.0f;
        mem = (BETA * mem + syn) * (1.0f - reset);
        s[(size_t)t * (BATCH * D1)] = (mem > THR) ? 1.0f : 0.0f;
    }
}

// ---------------------------------------------------------------------------
// Kernel 3: fused layer-2 GEMM + LIF scan.
//   One block per batch b (512 blocks, 512 threads). W2 [20,512] in smem.
//   Per t: load s1 row (double-buffered), 20 warp-shuffle dot products,
//   lane 0 of each warp carries LIF state for its output(s).
//   Warp w owns output o=w (w<16... all 16 warps own o=w), warps 0..3 also own o=16+w.
// ---------------------------------------------------------------------------
__global__ __launch_bounds__(512)
void k_layer2(const float* __restrict__ s1, const float* __restrict__ W2,
              float* __restrict__ out0, float* __restrict__ out2) {
    __shared__ float W2s[D2 * D1];   // 40 KB
    __shared__ float row[2][D1];     // 4 KB, double-buffered

    const int b   = blockIdx.x;
    const int tid = threadIdx.x;
    const int warp = tid >> 5;
    const int lane = tid & 31;

    for (int i = tid; i < D2 * D1; i += 512) W2s[i] = W2[i];
    __syncthreads();

    const int o0 = warp;               // outputs 0..15
    const int o1 = 16 + warp;          // outputs 16..19 (warps 0..3 only)
    const bool has1 = (warp < 4);

    float syn0 = 0.0f, mem0 = 0.0f;
    float syn1 = 0.0f, mem1 = 0.0f;

    const float* w0 = &W2s[o0 * D1];
    const float* w1 = has1 ? &W2s[o1 * D1] : &W2s[0];

    for (int t = 0; t < T_STEPS; t++) {
        float* buf = row[t & 1];
        buf[tid] = s1[((size_t)t * BATCH + b) * D1 + tid];
        __syncthreads();

        float d0 = 0.0f, d1 = 0.0f;
        #pragma unroll
        for (int j = 0; j < 16; j++) {
            float v = buf[lane + j * 32];
            d0 += v * w0[lane + j * 32];
            d1 += v * w1[lane + j * 32];
        }
        #pragma unroll
        for (int off = 16; off > 0; off >>= 1) {
            d0 += __shfl_down_sync(0xFFFFFFFFu, d0, off);
            d1 += __shfl_down_sync(0xFFFFFFFFu, d1, off);
        }

        if (lane == 0) {
            // output o0
            syn0 = ALPHA * syn0 + d0;
            float r0 = (mem0 > THR) ? 1.0f : 0.0f;
            mem0 = (BETA * mem0 + syn0) * (1.0f - r0);
            float sp0 = (mem0 > THR) ? 1.0f : 0.0f;
            size_t oidx0 = ((size_t)t * BATCH + b) * D2 + o0;
            out0[oidx0] = sp0;
            out2[oidx0] = sp0;

            if (has1) {
                syn1 = ALPHA * syn1 + d1;
                float r1 = (mem1 > THR) ? 1.0f : 0.0f;
                mem1 = (BETA * mem1 + syn1) * (1.0f - r1);
                float sp1 = (mem1 > THR) ? 1.0f : 0.0f;
                size_t oidx1 = ((size_t)t * BATCH + b) * D2 + o1;
                out0[oidx1] = sp1;
                out2[oidx1] = sp1;
            }
        }
        // No second barrier needed: double buffer + the t+1 barrier orders
        // reads of buf[t&1] before writes at t+2.
    }
}

// ---------------------------------------------------------------------------
// Launch
// ---------------------------------------------------------------------------
extern "C" void kernel_launch(void* const* d_in, const int* in_sizes, int n_in,
                              void* d_out, int out_size) {
    const float* x  = (const float*)d_in[0];   // [100, 512, 700]
    const float* W1 = (const float*)d_in[1];   // [512, 700]
    const float* W2 = (const float*)d_in[2];   // [20, 512]

    float* out  = (float*)d_out;
    float* out0 = out;                          // s2, copy 1
    float* s1   = out + S2_ELEMS;               // s1 (also layer-2 input)
    float* out2 = out + S2_ELEMS + S1_ELEMS;    // s2, copy 2

    // 0) transpose W1
    k_transpose_w1<<<(D0 * D1 + 255) / 256, 256>>>(W1);

    // 1) pre1 = x @ W1^T   (51200 x 512 x 700)
    dim3 grid(D1 / 128, M_TOT / 128);   // (4, 400)
    k_sgemm<<<grid, 256>>>(x);

    // 2) layer-1 scan -> s1
    k_scan1<<<(BATCH * D1 + 255) / 256, 256>>>(s1);

    // 3) fused layer-2 GEMM + scan -> s2 (both copies)
    k_layer2<<<BATCH, 512>>>(s1, W2, out0, out2);
}

// round 7
// speedup vs baseline: 2.3171x; 2.3171x over previous
#include <cuda_runtime.h>
#include <cuda_fp16.h>
#include <cstdint>

#define T_STEPS 100
#define BATCH   512
#define D0      700
#define D1      512
#define D2      20
#define M_TOT   (T_STEPS * BATCH)          // 51200
#define K_PAD   704                        // 700 padded to multiple of 32

#define S2_ELEMS (T_STEPS * BATCH * D2)    // 1,024,000
#define S1_ELEMS (T_STEPS * BATCH * D1)    // 26,214,400

#define ALPHA 0.8f
#define BETA  0.9f
#define THR   1.0f
#define W_SCALE     16.0f
#define INV_W_SCALE 0.0625f

// ---------------------------------------------------------------------------
// Scratch (__device__ globals; allocation-free rule)
// ---------------------------------------------------------------------------
__device__ float  g_pre1[(size_t)M_TOT * D1];   // 104.9 MB
__device__ float  g_pre2[(size_t)M_TOT * D2];   // 4.1 MB
__device__ __half g_xh[(size_t)M_TOT * K_PAD];  // 72 MB
__device__ __half g_xl[(size_t)M_TOT * K_PAD];  // 72 MB
__device__ __half g_wh[(size_t)D1 * K_PAD];     // 0.72 MB  (holds 16*W1 hi)
__device__ __half g_wl[(size_t)D1 * K_PAD];     // 0.72 MB  (holds 16*W1 lo)

// ---------------------------------------------------------------------------
// PTX helpers (compute_100-safe subset: cp.async, ldmatrix, mma.sync)
// ---------------------------------------------------------------------------
__device__ __forceinline__ uint32_t smem_to_u32(const void* p) {
    uint32_t a;
    asm("{ .reg .u64 t; cvta.to.shared.u64 t, %1; cvt.u32.u64 %0, t; }"
        : "=r"(a) : "l"(p));
    return a;
}

#define CP_ASYNC16(dst_u32, src_ptr) \
    asm volatile("cp.async.ca.shared.global [%0], [%1], 16;" \
                 :: "r"(dst_u32), "l"(src_ptr) : "memory")
#define CP_COMMIT() asm volatile("cp.async.commit_group;" ::: "memory")
#define CP_WAIT1()  asm volatile("cp.async.wait_group 1;" ::: "memory")
#define CP_WAIT0()  asm volatile("cp.async.wait_group 0;" ::: "memory")

#define LDSM4(r, addr) \
    asm volatile("ldmatrix.sync.aligned.m8n8.x4.shared.b16 {%0,%1,%2,%3}, [%4];" \
                 : "=r"((r)[0]), "=r"((r)[1]), "=r"((r)[2]), "=r"((r)[3]) \
                 : "r"(addr))

#define MMA16816(d, a, b0, b1) \
    asm volatile("mma.sync.aligned.m16n8k16.row.col.f32.f16.f16.f32 " \
                 "{%0,%1,%2,%3}, {%4,%5,%6,%7}, {%8,%9}, {%0,%1,%2,%3};" \
                 : "+f"((d)[0]), "+f"((d)[1]), "+f"((d)[2]), "+f"((d)[3]) \
                 : "r"((a)[0]), "r"((a)[1]), "r"((a)[2]), "r"((a)[3]), \
                   "r"(b0), "r"(b1))

// ---------------------------------------------------------------------------
// Prep: split fp32 -> (fp16 hi, fp16 lo), optional scale, zero-pad K 700->704.
// One thread per 4-float chunk (176 chunks per row; chunk 175 is padding).
// ---------------------------------------------------------------------------
__device__ __forceinline__ void split4h(float4 v, float sc, ushort4& h, ushort4& l) {
    float a0 = v.x * sc, a1 = v.y * sc, a2 = v.z * sc, a3 = v.w * sc;
    __half h0 = __float2half_rn(a0);
    __half h1 = __float2half_rn(a1);
    __half h2 = __float2half_rn(a2);
    __half h3 = __float2half_rn(a3);
    __half l0 = __float2half_rn(a0 - __half2float(h0));
    __half l1 = __float2half_rn(a1 - __half2float(h1));
    __half l2 = __float2half_rn(a2 - __half2float(h2));
    __half l3 = __float2half_rn(a3 - __half2float(h3));
    h = make_ushort4(__half_as_ushort(h0), __half_as_ushort(h1),
                     __half_as_ushort(h2), __half_as_ushort(h3));
    l = make_ushort4(__half_as_ushort(l0), __half_as_ushort(l1),
                     __half_as_ushort(l2), __half_as_ushort(l3));
}

__global__ void k_split_x(const float* __restrict__ x) {
    int u = blockIdx.x * 256 + threadIdx.x;
    if (u >= M_TOT * 176) return;
    int m = u / 176, c = u - m * 176;
    float4 v = make_float4(0.f, 0.f, 0.f, 0.f);
    if (c < 175) v = *reinterpret_cast<const float4*>(x + (size_t)m * D0 + c * 4);
    ushort4 h, l;
    split4h(v, 1.0f, h, l);
    size_t o = (size_t)m * K_PAD + c * 4;
    *reinterpret_cast<ushort4*>(reinterpret_cast<unsigned short*>(g_xh) + o) = h;
    *reinterpret_cast<ushort4*>(reinterpret_cast<unsigned short*>(g_xl) + o) = l;
}

__global__ void k_split_w(const float* __restrict__ W1) {
    int u = blockIdx.x * 256 + threadIdx.x;
    if (u >= D1 * 176) return;
    int n = u / 176, c = u - n * 176;
    float4 v = make_float4(0.f, 0.f, 0.f, 0.f);
    if (c < 175) v = *reinterpret_cast<const float4*>(W1 + (size_t)n * D0 + c * 4);
    ushort4 h, l;
    split4h(v, W_SCALE, h, l);   // scale keeps wl out of fp16 subnormals
    size_t o = (size_t)n * K_PAD + c * 4;
    *reinterpret_cast<ushort4*>(reinterpret_cast<unsigned short*>(g_wh) + o) = h;
    *reinterpret_cast<ushort4*>(reinterpret_cast<unsigned short*>(g_wl) + o) = l;
}

// ---------------------------------------------------------------------------
// GEMM1: mma.sync fp16 3-split with per-k-step accumulator draining.
//   pre1*16 = x @ (16*W1)^T
//   Block 128(M) x 128(N), BK=32, 512 threads (16 warps, 4x4 warp grid,
//   warp tile 32x32).  cp.async double buffer; ldmatrix fragment loads.
//   Per K=16 step: zero partial P, 3 split MMAs into P (short RZ chain),
//   then tot += P in CUDA-core fp32 (RN). This bounds the tensor-core
//   truncating-accumulator bias that broke Round 6.
// ---------------------------------------------------------------------------
#define BK       32
#define N_STAGES (K_PAD / BK)      // 22
#define ROW_B    80                // bytes per smem row (40 halfs)
#define TILEB    (128 * ROW_B)     // 10240 per tile
#define AH_T     0
#define AL_T     TILEB
#define BH_T     (2 * TILEB)
#define BL_T     (3 * TILEB)
#define STAGEB   (4 * TILEB)       // 40960
#define G1_SMEM  (2 * STAGEB)      // 81920

__global__ __launch_bounds__(512, 1)
void k_gemm1() {
    extern __shared__ char smem[];
    const uint32_t sb = smem_to_u32(smem);
    const int tid  = threadIdx.x;
    const int lane = tid & 31;
    const int wid  = tid >> 5;
    const int wm   = wid >> 2;      // 0..3 (M)
    const int wn   = wid & 3;       // 0..3 (N)

    const int m0 = blockIdx.y * 128;
    const int n0 = blockIdx.x * 128;

    // ---- cp.async source/dst mapping: each thread loads (r, q) in all 4 tiles
    const int r = tid >> 2;         // 0..127
    const int q = tid & 3;          // 0..3  (16B chunk within 64B of K)
    const __half* srcA_h = g_xh + (size_t)(m0 + r) * K_PAD + q * 8;
    const __half* srcA_l = g_xl + (size_t)(m0 + r) * K_PAD + q * 8;
    const __half* srcB_h = g_wh + (size_t)(n0 + r) * K_PAD + q * 8;
    const __half* srcB_l = g_wl + (size_t)(n0 + r) * K_PAD + q * 8;
    const uint32_t dst_rq = (uint32_t)(r * ROW_B + q * 16);

    // ---- ldmatrix lane addressing
    const int a_row  = lane & 15;
    const int a_cb   = (lane >> 4) * 16;                       // byte col
    const int b_row  = (lane & 7) + ((lane >> 4) & 1) * 8;
    const int b_cb   = ((lane >> 3) & 1) * 16;
    uint32_t aOff[2], bOff[2];
    #pragma unroll
    for (int i = 0; i < 2; i++)
        aOff[i] = (uint32_t)((wm * 32 + i * 16 + a_row) * ROW_B + a_cb);
    #pragma unroll
    for (int jp = 0; jp < 2; jp++)
        bOff[jp] = (uint32_t)((wn * 32 + jp * 16 + b_row) * ROW_B + b_cb);

    float tot[2][4][4] = {};

    // ---- prologue: stage 0
    {
        uint32_t d = sb + dst_rq;
        CP_ASYNC16(d + AH_T, srcA_h);
        CP_ASYNC16(d + AL_T, srcA_l);
        CP_ASYNC16(d + BH_T, srcB_h);
        CP_ASYNC16(d + BL_T, srcB_l);
        CP_COMMIT();
    }

    for (int s = 0; s < N_STAGES; s++) {
        if (s + 1 < N_STAGES) {
            size_t ko = (size_t)(s + 1) * BK;
            uint32_t d = sb + ((s + 1) & 1) * STAGEB + dst_rq;
            CP_ASYNC16(d + AH_T, srcA_h + ko);
            CP_ASYNC16(d + AL_T, srcA_l + ko);
            CP_ASYNC16(d + BH_T, srcB_h + ko);
            CP_ASYNC16(d + BL_T, srcB_l + ko);
            CP_COMMIT();
            CP_WAIT1();
        } else {
            CP_WAIT0();
        }
        __syncthreads();

        const uint32_t base = sb + (s & 1) * STAGEB;
        #pragma unroll
        for (int ks = 0; ks < 2; ks++) {
            const uint32_t kb = ks * 32;   // 16 halfs = 32 bytes
            uint32_t ah[2][4], al[2][4], bh[2][4], bl[2][4];
            #pragma unroll
            for (int i = 0; i < 2; i++) {
                LDSM4(ah[i], base + AH_T + aOff[i] + kb);
                LDSM4(al[i], base + AL_T + aOff[i] + kb);
            }
            #pragma unroll
            for (int jp = 0; jp < 2; jp++) {
                LDSM4(bh[jp], base + BH_T + bOff[jp] + kb);
                LDSM4(bl[jp], base + BL_T + bOff[jp] + kb);
            }

            // Short-lived MMA partial: bounds truncating-accumulator chain to
            // 3 adds at per-k-step magnitude, then drains to fp32 RN totals.
            float P[2][4][4];
            #pragma unroll
            for (int i = 0; i < 2; i++)
                #pragma unroll
                for (int j = 0; j < 4; j++)
                    #pragma unroll
                    for (int e = 0; e < 4; e++) P[i][j][e] = 0.0f;

            #pragma unroll
            for (int i = 0; i < 2; i++) {
                #pragma unroll
                for (int j = 0; j < 4; j++) {
                    const int jp = j >> 1, e = (j & 1) * 2;
                    MMA16816(P[i][j], ah[i], bh[jp][e], bh[jp][e + 1]);
                    MMA16816(P[i][j], ah[i], bl[jp][e], bl[jp][e + 1]);
                    MMA16816(P[i][j], al[i], bh[jp][e], bh[jp][e + 1]);
                }
            }

            #pragma unroll
            for (int i = 0; i < 2; i++)
                #pragma unroll
                for (int j = 0; j < 4; j++)
                    #pragma unroll
                    for (int e = 0; e < 4; e++) tot[i][j][e] += P[i][j][e];
        }
        __syncthreads();
    }

    // ---- epilogue
    const int g  = lane >> 2;
    const int tg = lane & 3;
    #pragma unroll
    for (int i = 0; i < 2; i++) {
        const int m = m0 + wm * 32 + i * 16 + g;
        #pragma unroll
        for (int j = 0; j < 4; j++) {
            const int n = n0 + wn * 32 + j * 8 + tg * 2;
            *reinterpret_cast<float2*>(g_pre1 + (size_t)m * D1 + n) =
                make_float2(tot[i][j][0], tot[i][j][1]);
            *reinterpret_cast<float2*>(g_pre1 + (size_t)(m + 8) * D1 + n) =
                make_float2(tot[i][j][2], tot[i][j][3]);
        }
    }
}

// ---------------------------------------------------------------------------
// Layer-1 LIF scan (pre1 carries 16x scale; undo with exact *1/16).
// ---------------------------------------------------------------------------
__global__ void k_scan1(float* __restrict__ s1) {
    int idx = blockIdx.x * blockDim.x + threadIdx.x;
    if (idx >= BATCH * D1) return;

    float syn = 0.0f, mem = 0.0f;
    const float* p = g_pre1 + idx;
    float* s = s1 + idx;

    #pragma unroll 4
    for (int t = 0; t < T_STEPS; t++) {
        float pr = p[(size_t)t * (BATCH * D1)] * INV_W_SCALE;
        syn = ALPHA * syn + pr;
        float reset = (mem > THR) ? 1.0f : 0.0f;
        mem = (BETA * mem + syn) * (1.0f - reset);
        s[(size_t)t * (BATCH * D1)] = (mem > THR) ? 1.0f : 0.0f;
    }
}

// ---------------------------------------------------------------------------
// GEMM2: pre2[m, o2] = s1[m, :] . W2[o2, :]   (M=51200, K=512, N=20)
//   Warp handles 4 rows; s1 rows register-cached; W2 smem-resident.
// ---------------------------------------------------------------------------
__global__ __launch_bounds__(256)
void k_gemm2(const float* __restrict__ s1, const float* __restrict__ W2) {
    __shared__ float W2s[D2 * D1];   // 40 KB
    const int tid = threadIdx.x;
    const int warp = tid >> 5;
    const int lane = tid & 31;

    for (int i = tid; i < D2 * D1; i += 256) W2s[i] = W2[i];
    __syncthreads();

    const int row0 = blockIdx.x * 32 + warp * 4;

    float xr[4][16];
    #pragma unroll
    for (int r = 0; r < 4; r++) {
        const float* p = s1 + (size_t)(row0 + r) * D1;
        #pragma unroll
        for (int i = 0; i < 16; i++) xr[r][i] = p[i * 32 + lane];
    }

    for (int o = 0; o < D2; o++) {
        const float* wrow = W2s + o * D1;
        float a0 = 0.f, a1 = 0.f, a2 = 0.f, a3 = 0.f;
        #pragma unroll
        for (int i = 0; i < 16; i++) {
            float w = wrow[i * 32 + lane];
            a0 = fmaf(xr[0][i], w, a0);
            a1 = fmaf(xr[1][i], w, a1);
            a2 = fmaf(xr[2][i], w, a2);
            a3 = fmaf(xr[3][i], w, a3);
        }
        #pragma unroll
        for (int off = 16; off > 0; off >>= 1) {
            a0 += __shfl_down_sync(0xFFFFFFFFu, a0, off);
            a1 += __shfl_down_sync(0xFFFFFFFFu, a1, off);
            a2 += __shfl_down_sync(0xFFFFFFFFu, a2, off);
            a3 += __shfl_down_sync(0xFFFFFFFFu, a3, off);
        }
        if (lane == 0) {
            size_t base = (size_t)row0 * D2 + o;
            g_pre2[base +      0] = a0;
            g_pre2[base +     D2] = a1;
            g_pre2[base + 2 * D2] = a2;
            g_pre2[base + 3 * D2] = a3;
        }
    }
}

// ---------------------------------------------------------------------------
// Layer-2 LIF scan: 10240 lanes, writes both s2 copies.
// ---------------------------------------------------------------------------
__global__ void k_scan2(float* __restrict__ out0, float* __restrict__ out2) {
    int idx = blockIdx.x * blockDim.x + threadIdx.x;
    if (idx >= BATCH * D2) return;

    float syn = 0.0f, mem = 0.0f;
    const float* p = g_pre2 + idx;

    #pragma unroll 4
    for (int t = 0; t < T_STEPS; t++) {
        float pr = p[(size_t)t * (BATCH * D2)];
        syn = ALPHA * syn + pr;
        float reset = (mem > THR) ? 1.0f : 0.0f;
        mem = (BETA * mem + syn) * (1.0f - reset);
        float sp = (mem > THR) ? 1.0f : 0.0f;
        out0[(size_t)t * (BATCH * D2) + idx] = sp;
        out2[(size_t)t * (BATCH * D2) + idx] = sp;
    }
}

// ---------------------------------------------------------------------------
// Launch
// ---------------------------------------------------------------------------
extern "C" void kernel_launch(void* const* d_in, const int* in_sizes, int n_in,
                              void* d_out, int out_size) {
    const float* x  = (const float*)d_in[0];   // [100, 512, 700]
    const float* W1 = (const float*)d_in[1];   // [512, 700]
    const float* W2 = (const float*)d_in[2];   // [20, 512]

    float* out  = (float*)d_out;
    float* out0 = out;                          // s2, copy 1
    float* s1   = out + S2_ELEMS;               // s1 (also layer-2 input)
    float* out2 = out + S2_ELEMS + S1_ELEMS;    // s2, copy 2

    cudaFuncSetAttribute(k_gemm1, cudaFuncAttributeMaxDynamicSharedMemorySize, G1_SMEM);

    // 0) fp32 -> fp16 hi/lo splits (W1 pre-scaled by 16; zero-padded K)
    k_split_x<<<(M_TOT * 176 + 255) / 256, 256>>>(x);
    k_split_w<<<(D1 * 176 + 255) / 256, 256>>>(W1);

    // 1) pre1*16 = x @ (16*W1)^T via mma.sync (3-split fp16, drained accum)
    dim3 g1(D1 / 128, M_TOT / 128);             // (4, 400)
    k_gemm1<<<g1, 512, G1_SMEM>>>();

    // 2) layer-1 scan -> s1 (applies exact 1/16)
    k_scan1<<<(BATCH * D1 + 255) / 256, 256>>>(s1);

    // 3) pre2 = s1 @ W2^T
    k_gemm2<<<M_TOT / 32, 256>>>(s1, W2);

    // 4) layer-2 scan -> s2 (both copies)
    k_scan2<<<(BATCH * D2 + 255) / 256, 256>>>(out0, out2);
}

// round 9
// speedup vs baseline: 2.4151x; 1.0423x over previous
#include <cuda_runtime.h>
#include <cuda_fp16.h>
#include <cstdint>

#define T_STEPS 100
#define BATCH   512
#define D0      700
#define D1      512
#define D2      20
#define D2P     32                         // D2 padded for MMA
#define M_TOT   (T_STEPS * BATCH)          // 51200
#define K_PAD   704                        // 700 padded to multiple of 32

#define S2_ELEMS (T_STEPS * BATCH * D2)    // 1,024,000
#define S1_ELEMS (T_STEPS * BATCH * D1)    // 26,214,400

#define ALPHA 0.8f
#define BETA  0.9f
#define THR   1.0f
#define W_SCALE     16.0f
#define INV_W_SCALE 0.0625f

// ---------------------------------------------------------------------------
// Scratch (__device__ globals; allocation-free rule)
// ---------------------------------------------------------------------------
__device__ float  g_pre1[(size_t)M_TOT * D1];   // 104.9 MB
__device__ float  g_pre2[(size_t)M_TOT * D2];   // 4.1 MB
__device__ __half g_xh[(size_t)M_TOT * K_PAD];  // 72 MB
__device__ __half g_xl[(size_t)M_TOT * K_PAD];  // 72 MB
__device__ __half g_wh[(size_t)D1 * K_PAD];     // (16*W1) hi
__device__ __half g_wl[(size_t)D1 * K_PAD];     // (16*W1) lo
__device__ __half g_s1h[(size_t)S1_ELEMS];      // 52 MB, fp16 copy of s1
__device__ __half g_w2h[(size_t)D2P * D1];      // (16*W2) hi, padded rows zero
__device__ __half g_w2l[(size_t)D2P * D1];      // (16*W2) lo

// ---------------------------------------------------------------------------
// PTX helpers (compute_100-safe subset: cp.async, ldmatrix, mma.sync)
// ---------------------------------------------------------------------------
__device__ __forceinline__ uint32_t smem_to_u32(const void* p) {
    uint32_t a;
    asm("{ .reg .u64 t; cvta.to.shared.u64 t, %1; cvt.u32.u64 %0, t; }"
        : "=r"(a) : "l"(p));
    return a;
}

#define CP_ASYNC16(dst_u32, src_ptr) \
    asm volatile("cp.async.ca.shared.global [%0], [%1], 16;" \
                 :: "r"(dst_u32), "l"(src_ptr) : "memory")
#define CP_COMMIT() asm volatile("cp.async.commit_group;" ::: "memory")
#define CP_WAIT1()  asm volatile("cp.async.wait_group 1;" ::: "memory")
#define CP_WAIT0()  asm volatile("cp.async.wait_group 0;" ::: "memory")

#define LDSM4(r, addr) \
    asm volatile("ldmatrix.sync.aligned.m8n8.x4.shared.b16 {%0,%1,%2,%3}, [%4];" \
                 : "=r"((r)[0]), "=r"((r)[1]), "=r"((r)[2]), "=r"((r)[3]) \
                 : "r"(addr))

// d += a*b (accumulate in place)
#define MMA16816(d, a, b0, b1) \
    asm volatile("mma.sync.aligned.m16n8k16.row.col.f32.f16.f16.f32 " \
                 "{%0,%1,%2,%3}, {%4,%5,%6,%7}, {%8,%9}, {%0,%1,%2,%3};" \
                 : "+f"((d)[0]), "+f"((d)[1]), "+f"((d)[2]), "+f"((d)[3]) \
                 : "r"((a)[0]), "r"((a)[1]), "r"((a)[2]), "r"((a)[3]), \
                   "r"(b0), "r"(b1))

// d = a*b + 0 (fresh partial; C = zero regs -> no explicit zeroing MOVs)
#define MMA16816_Z(d, a, b0, b1) \
    asm volatile("mma.sync.aligned.m16n8k16.row.col.f32.f16.f16.f32 " \
                 "{%0,%1,%2,%3}, {%4,%5,%6,%7}, {%8,%9}, {%10,%11,%12,%13};" \
                 : "=f"((d)[0]), "=f"((d)[1]), "=f"((d)[2]), "=f"((d)[3]) \
                 : "r"((a)[0]), "r"((a)[1]), "r"((a)[2]), "r"((a)[3]), \
                   "r"(b0), "r"(b1), \
                   "f"(0.0f), "f"(0.0f), "f"(0.0f), "f"(0.0f))

// ---------------------------------------------------------------------------
// Prep: split fp32 -> (fp16 hi, fp16 lo), optional scale, zero-pad K.
// ---------------------------------------------------------------------------
__device__ __forceinline__ void split4h(float4 v, float sc, ushort4& h, ushort4& l) {
    float a0 = v.x * sc, a1 = v.y * sc, a2 = v.z * sc, a3 = v.w * sc;
    __half h0 = __float2half_rn(a0);
    __half h1 = __float2half_rn(a1);
    __half h2 = __float2half_rn(a2);
    __half h3 = __float2half_rn(a3);
    __half l0 = __float2half_rn(a0 - __half2float(h0));
    __half l1 = __float2half_rn(a1 - __half2float(h1));
    __half l2 = __float2half_rn(a2 - __half2float(h2));
    __half l3 = __float2half_rn(a3 - __half2float(h3));
    h = make_ushort4(__half_as_ushort(h0), __half_as_ushort(h1),
                     __half_as_ushort(h2), __half_as_ushort(h3));
    l = make_ushort4(__half_as_ushort(l0), __half_as_ushort(l1),
                     __half_as_ushort(l2), __half_as_ushort(l3));
}

__global__ void k_split_x(const float* __restrict__ x) {
    int u = blockIdx.x * 256 + threadIdx.x;
    if (u >= M_TOT * 176) return;
    int m = u / 176, c = u - m * 176;
    float4 v = make_float4(0.f, 0.f, 0.f, 0.f);
    if (c < 175) v = *reinterpret_cast<const float4*>(x + (size_t)m * D0 + c * 4);
    ushort4 h, l;
    split4h(v, 1.0f, h, l);
    size_t o = (size_t)m * K_PAD + c * 4;
    *reinterpret_cast<ushort4*>(reinterpret_cast<unsigned short*>(g_xh) + o) = h;
    *reinterpret_cast<ushort4*>(reinterpret_cast<unsigned short*>(g_xl) + o) = l;
}

__global__ void k_split_w(const float* __restrict__ W1) {
    int u = blockIdx.x * 256 + threadIdx.x;
    if (u >= D1 * 176) return;
    int n = u / 176, c = u - n * 176;
    float4 v = make_float4(0.f, 0.f, 0.f, 0.f);
    if (c < 175) v = *reinterpret_cast<const float4*>(W1 + (size_t)n * D0 + c * 4);
    ushort4 h, l;
    split4h(v, W_SCALE, h, l);   // scale keeps wl out of fp16 subnormals
    size_t o = (size_t)n * K_PAD + c * 4;
    *reinterpret_cast<ushort4*>(reinterpret_cast<unsigned short*>(g_wh) + o) = h;
    *reinterpret_cast<ushort4*>(reinterpret_cast<unsigned short*>(g_wl) + o) = l;
}

// W2 [20,512] -> (16*W2) hi/lo fp16, padded to 32 rows (zeros).
__global__ void k_split_w2(const float* __restrict__ W2) {
    int u = blockIdx.x * 256 + threadIdx.x;          // one per 4 elems
    if (u >= D2P * D1 / 4) return;
    int n = u / (D1 / 4), c = u - n * (D1 / 4);
    float4 v = make_float4(0.f, 0.f, 0.f, 0.f);
    if (n < D2) v = *reinterpret_cast<const float4*>(W2 + (size_t)n * D1 + c * 4);
    ushort4 h, l;
    split4h(v, W_SCALE, h, l);
    size_t o = (size_t)n * D1 + c * 4;
    *reinterpret_cast<ushort4*>(reinterpret_cast<unsigned short*>(g_w2h) + o) = h;
    *reinterpret_cast<ushort4*>(reinterpret_cast<unsigned short*>(g_w2l) + o) = l;
}

// ---------------------------------------------------------------------------
// GEMM1: mma.sync fp16 3-split, per-k-step drained partials.
//   pre1*16 = x @ (16*W1)^T.  Block 128x128, BK=32, 512 thr, 4x4 warps.
//   Per (i,j) sub-tile: P = ah*bh + 0; P += ah*bl; P += al*bh; tot += P.
// ---------------------------------------------------------------------------
#define BK       32
#define N_STAGES (K_PAD / BK)      // 22
#define ROW_B    80                // bytes per smem row (40 halfs)
#define TILEB    (128 * ROW_B)     // 10240 per tile
#define AH_T     0
#define AL_T     TILEB
#define BH_T     (2 * TILEB)
#define BL_T     (3 * TILEB)
#define STAGEB   (4 * TILEB)       // 40960
#define G1_SMEM  (2 * STAGEB)      // 81920

__global__ __launch_bounds__(512, 1)
void k_gemm1() {
    extern __shared__ char smem[];
    const uint32_t sb = smem_to_u32(smem);
    const int tid  = threadIdx.x;
    const int lane = tid & 31;
    const int wid  = tid >> 5;
    const int wm   = wid >> 2;      // 0..3 (M)
    const int wn   = wid & 3;       // 0..3 (N)

    const int m0 = blockIdx.y * 128;
    const int n0 = blockIdx.x * 128;

    const int r = tid >> 2;         // 0..127
    const int q = tid & 3;          // 16B chunk in 64B of K
    const __half* srcA_h = g_xh + (size_t)(m0 + r) * K_PAD + q * 8;
    const __half* srcA_l = g_xl + (size_t)(m0 + r) * K_PAD + q * 8;
    const __half* srcB_h = g_wh + (size_t)(n0 + r) * K_PAD + q * 8;
    const __half* srcB_l = g_wl + (size_t)(n0 + r) * K_PAD + q * 8;
    const uint32_t dst_rq = (uint32_t)(r * ROW_B + q * 16);

    const int a_row  = lane & 15;
    const int a_cb   = (lane >> 4) * 16;
    const int b_row  = (lane & 7) + ((lane >> 4) & 1) * 8;
    const int b_cb   = ((lane >> 3) & 1) * 16;
    uint32_t aOff[2], bOff[2];
    #pragma unroll
    for (int i = 0; i < 2; i++)
        aOff[i] = (uint32_t)((wm * 32 + i * 16 + a_row) * ROW_B + a_cb);
    #pragma unroll
    for (int jp = 0; jp < 2; jp++)
        bOff[jp] = (uint32_t)((wn * 32 + jp * 16 + b_row) * ROW_B + b_cb);

    float tot[2][4][4] = {};

    {   // prologue: stage 0
        uint32_t d = sb + dst_rq;
        CP_ASYNC16(d + AH_T, srcA_h);
        CP_ASYNC16(d + AL_T, srcA_l);
        CP_ASYNC16(d + BH_T, srcB_h);
        CP_ASYNC16(d + BL_T, srcB_l);
        CP_COMMIT();
    }

    for (int s = 0; s < N_STAGES; s++) {
        if (s + 1 < N_STAGES) {
            size_t ko = (size_t)(s + 1) * BK;
            uint32_t d = sb + ((s + 1) & 1) * STAGEB + dst_rq;
            CP_ASYNC16(d + AH_T, srcA_h + ko);
            CP_ASYNC16(d + AL_T, srcA_l + ko);
            CP_ASYNC16(d + BH_T, srcB_h + ko);
            CP_ASYNC16(d + BL_T, srcB_l + ko);
            CP_COMMIT();
            CP_WAIT1();
        } else {
            CP_WAIT0();
        }
        __syncthreads();

        const uint32_t base = sb + (s & 1) * STAGEB;
        #pragma unroll
        for (int ks = 0; ks < 2; ks++) {
            const uint32_t kb = ks * 32;
            uint32_t ah[2][4], al[2][4], bh[2][4], bl[2][4];
            #pragma unroll
            for (int i = 0; i < 2; i++) {
                LDSM4(ah[i], base + AH_T + aOff[i] + kb);
                LDSM4(al[i], base + AL_T + aOff[i] + kb);
            }
            #pragma unroll
            for (int jp = 0; jp < 2; jp++) {
                LDSM4(bh[jp], base + BH_T + bOff[jp] + kb);
                LDSM4(bl[jp], base + BL_T + bOff[jp] + kb);
            }

            #pragma unroll
            for (int i = 0; i < 2; i++) {
                #pragma unroll
                for (int j = 0; j < 4; j++) {
                    const int jp = j >> 1, e = (j & 1) * 2;
                    float P[4];
                    MMA16816_Z(P, ah[i], bh[jp][e], bh[jp][e + 1]);
                    MMA16816(P, ah[i], bl[jp][e], bl[jp][e + 1]);
                    MMA16816(P, al[i], bh[jp][e], bh[jp][e + 1]);
                    tot[i][j][0] += P[0];
                    tot[i][j][1] += P[1];
                    tot[i][j][2] += P[2];
                    tot[i][j][3] += P[3];
                }
            }
        }
        __syncthreads();
    }

    const int g  = lane >> 2;
    const int tg = lane & 3;
    #pragma unroll
    for (int i = 0; i < 2; i++) {
        const int m = m0 + wm * 32 + i * 16 + g;
        #pragma unroll
        for (int j = 0; j < 4; j++) {
            const int n = n0 + wn * 32 + j * 8 + tg * 2;
            *reinterpret_cast<float2*>(g_pre1 + (size_t)m * D1 + n) =
                make_float2(tot[i][j][0], tot[i][j][1]);
            *reinterpret_cast<float2*>(g_pre1 + (size_t)(m + 8) * D1 + n) =
                make_float2(tot[i][j][2], tot[i][j][3]);
        }
    }
}

// ---------------------------------------------------------------------------
// Layer-1 LIF scan. Writes fp32 s1 (output) and fp16 s1h (gemm2 input).
// ---------------------------------------------------------------------------
__global__ void k_scan1(float* __restrict__ s1) {
    int idx = blockIdx.x * blockDim.x + threadIdx.x;
    if (idx >= BATCH * D1) return;

    float syn = 0.0f, mem = 0.0f;
    const float* p = g_pre1 + idx;
    float* s = s1 + idx;
    __half* sh = g_s1h + idx;

    #pragma unroll 4
    for (int t = 0; t < T_STEPS; t++) {
        float pr = p[(size_t)t * (BATCH * D1)] * INV_W_SCALE;
        syn = ALPHA * syn + pr;
        float reset = (mem > THR) ? 1.0f : 0.0f;
        mem = (BETA * mem + syn) * (1.0f - reset);
        float sp = (mem > THR) ? 1.0f : 0.0f;
        s[(size_t)t * (BATCH * D1)] = sp;
        sh[(size_t)t * (BATCH * D1)] = __float2half_rn(sp);   // exact (0 or 1)
    }
}

// ---------------------------------------------------------------------------
// GEMM2 via mma.sync: pre2*16 = s1h @ (16*W2)^T   (M=51200, K=512, N=32 pad)
//   Block = 128 thr (4 warps) x 64 rows.  K chunks of 128, single buffer.
//   FIXED vs R8: full 256 B/row cp.async fill (16 chunks/row, was 8).
// ---------------------------------------------------------------------------
#define G2_ROW_B 272                       // 128 halfs = 256 B, pad to 272
#define G2_A     0
#define G2_BH    (64 * G2_ROW_B)           // 17408
#define G2_BL    (G2_BH + 32 * G2_ROW_B)   // 26112
#define G2_SMEM  (G2_BL + 32 * G2_ROW_B)   // 34816

__global__ __launch_bounds__(128)
void k_gemm2() {
    __shared__ char smem[G2_SMEM];
    const uint32_t sb = smem_to_u32(smem);
    const int tid  = threadIdx.x;
    const int lane = tid & 31;
    const int wid  = tid >> 5;
    const int m0   = blockIdx.x * 64;

    const int a_row = lane & 15;
    const int a_cb  = (lane >> 4) * 16;
    const int b_row = (lane & 7) + ((lane >> 4) & 1) * 8;
    const int b_cb  = ((lane >> 3) & 1) * 16;
    const uint32_t aOff = (uint32_t)((wid * 16 + a_row) * G2_ROW_B + a_cb);
    uint32_t bOff[2];
    #pragma unroll
    for (int jp = 0; jp < 2; jp++)
        bOff[jp] = (uint32_t)((jp * 16 + b_row) * G2_ROW_B + b_cb);

    float tot[4][4] = {};

    for (int kc = 0; kc < 4; kc++) {
        const int k0 = kc * 128;
        // A: 64 rows x 16 16B-chunks = 1024 units -> 8/thread
        #pragma unroll
        for (int i = 0; i < 8; i++) {
            int u = tid + i * 128;
            int rr = u >> 4, qq = u & 15;
            CP_ASYNC16(sb + G2_A + rr * G2_ROW_B + qq * 16,
                       g_s1h + (size_t)(m0 + rr) * D1 + k0 + qq * 8);
        }
        // Bh/Bl: 32 rows x 16 chunks = 512 units -> 4/thread each
        #pragma unroll
        for (int i = 0; i < 4; i++) {
            int u = tid + i * 128;
            int rr = u >> 4, qq = u & 15;
            CP_ASYNC16(sb + G2_BH + rr * G2_ROW_B + qq * 16,
                       g_w2h + (size_t)rr * D1 + k0 + qq * 8);
            CP_ASYNC16(sb + G2_BL + rr * G2_ROW_B + qq * 16,
                       g_w2l + (size_t)rr * D1 + k0 + qq * 8);
        }
        CP_COMMIT();
        CP_WAIT0();
        __syncthreads();

        float Pc[4][4];
        #pragma unroll
        for (int ks = 0; ks < 8; ks++) {
            const uint32_t kb = ks * 32;
            uint32_t af[4], bhf[2][4], blf[2][4];
            LDSM4(af, sb + G2_A + aOff + kb);
            #pragma unroll
            for (int jp = 0; jp < 2; jp++) {
                LDSM4(bhf[jp], sb + G2_BH + bOff[jp] + kb);
                LDSM4(blf[jp], sb + G2_BL + bOff[jp] + kb);
            }
            #pragma unroll
            for (int j = 0; j < 4; j++) {
                const int jp = j >> 1, e = (j & 1) * 2;
                if (ks == 0) {
                    MMA16816_Z(Pc[j], af, bhf[jp][e], bhf[jp][e + 1]);
                } else {
                    MMA16816(Pc[j], af, bhf[jp][e], bhf[jp][e + 1]);
                }
                MMA16816(Pc[j], af, blf[jp][e], blf[jp][e + 1]);
            }
        }
        #pragma unroll
        for (int j = 0; j < 4; j++)
            #pragma unroll
            for (int e = 0; e < 4; e++) tot[j][e] += Pc[j][e];
        __syncthreads();
    }

    // epilogue: write n < 20 only
    const int g  = lane >> 2;
    const int tg = lane & 3;
    const int m  = m0 + wid * 16 + g;
    #pragma unroll
    for (int j = 0; j < 3; j++) {          // j=3 -> n>=24, all padded
        const int n = j * 8 + tg * 2;
        if (n + 1 < D2) {
            *reinterpret_cast<float2*>(g_pre2 + (size_t)m * D2 + n) =
                make_float2(tot[j][0], tot[j][1]);
            *reinterpret_cast<float2*>(g_pre2 + (size_t)(m + 8) * D2 + n) =
                make_float2(tot[j][2], tot[j][3]);
        }
    }
}

// ---------------------------------------------------------------------------
// Layer-2 LIF scan (pre2 carries 16x scale; undo exactly).
// ---------------------------------------------------------------------------
__global__ void k_scan2(float* __restrict__ out0, float* __restrict__ out2) {
    int idx = blockIdx.x * blockDim.x + threadIdx.x;
    if (idx >= BATCH * D2) return;

    float syn = 0.0f, mem = 0.0f;
    const float* p = g_pre2 + idx;

    #pragma unroll 4
    for (int t = 0; t < T_STEPS; t++) {
        float pr = p[(size_t)t * (BATCH * D2)] * INV_W_SCALE;
        syn = ALPHA * syn + pr;
        float reset = (mem > THR) ? 1.0f : 0.0f;
        mem = (BETA * mem + syn) * (1.0f - reset);
        float sp = (mem > THR) ? 1.0f : 0.0f;
        out0[(size_t)t * (BATCH * D2) + idx] = sp;
        out2[(size_t)t * (BATCH * D2) + idx] = sp;
    }
}

// ---------------------------------------------------------------------------
// Launch
// ---------------------------------------------------------------------------
extern "C" void kernel_launch(void* const* d_in, const int* in_sizes, int n_in,
                              void* d_out, int out_size) {
    const float* x  = (const float*)d_in[0];   // [100, 512, 700]
    const float* W1 = (const float*)d_in[1];   // [512, 700]
    const float* W2 = (const float*)d_in[2];   // [20, 512]

    float* out  = (float*)d_out;
    float* out0 = out;                          // s2, copy 1
    float* s1   = out + S2_ELEMS;               // s1
    float* out2 = out + S2_ELEMS + S1_ELEMS;    // s2, copy 2

    cudaFuncSetAttribute(k_gemm1, cudaFuncAttributeMaxDynamicSharedMemorySize, G1_SMEM);

    // 0) splits
    k_split_x<<<(M_TOT * 176 + 255) / 256, 256>>>(x);
    k_split_w<<<(D1 * 176 + 255) / 256, 256>>>(W1);
    k_split_w2<<<(D2P * D1 / 4 + 255) / 256, 256>>>(W2);

    // 1) pre1*16 = x @ (16*W1)^T
    dim3 g1(D1 / 128, M_TOT / 128);             // (4, 400)
    k_gemm1<<<g1, 512, G1_SMEM>>>();

    // 2) layer-1 scan -> s1 (fp32) + s1h (fp16)
    k_scan1<<<(BATCH * D1 + 255) / 256, 256>>>(s1);

    // 3) pre2*16 = s1h @ (16*W2)^T via mma.sync
    k_gemm2<<<M_TOT / 64, 128>>>();

    // 4) layer-2 scan -> s2 (both copies)
    k_scan2<<<(BATCH * D2 + 255) / 256, 256>>>(out0, out2);
}

// round 11
// speedup vs baseline: 2.4360x; 1.0087x over previous
#include <cuda_runtime.h>
#include <cuda_fp16.h>
#include <cstdint>

#define T_STEPS 100
#define BATCH   512
#define D0      700
#define D1      512
#define D2      20
#define D2P     32                         // D2 padded for MMA
#define M_TOT   (T_STEPS * BATCH)          // 51200
#define K_PAD   704                        // 700 padded to multiple of 32

#define S2_ELEMS (T_STEPS * BATCH * D2)    // 1,024,000
#define S1_ELEMS (T_STEPS * BATCH * D1)    // 26,214,400

#define ALPHA 0.8f
#define BETA  0.9f
#define THR   1.0f
#define W_SCALE     16.0f
#define INV_W_SCALE 0.0625f

// ---------------------------------------------------------------------------
// Scratch (__device__ globals; allocation-free rule)
// ---------------------------------------------------------------------------
__device__ float  g_pre1[(size_t)M_TOT * D1];   // 104.9 MB
__device__ float  g_pre2[(size_t)M_TOT * D2];   // 4.1 MB
__device__ __half g_xh[(size_t)M_TOT * K_PAD];  // 72 MB
__device__ __half g_xl[(size_t)M_TOT * K_PAD];  // 72 MB
__device__ __half g_wh[(size_t)D1 * K_PAD];     // (16*W1) hi
__device__ __half g_wl[(size_t)D1 * K_PAD];     // (16*W1) lo
__device__ __half g_s1h[(size_t)S1_ELEMS];      // 52 MB, fp16 copy of s1
__device__ __half g_w2h[(size_t)D2P * D1];      // (16*W2) hi, padded rows zero
__device__ __half g_w2l[(size_t)D2P * D1];      // (16*W2) lo

// ---------------------------------------------------------------------------
// PTX helpers (compute_100-safe subset: cp.async, ldmatrix, mma.sync)
// ---------------------------------------------------------------------------
__device__ __forceinline__ uint32_t smem_to_u32(const void* p) {
    uint32_t a;
    asm("{ .reg .u64 t; cvta.to.shared.u64 t, %1; cvt.u32.u64 %0, t; }"
        : "=r"(a) : "l"(p));
    return a;
}

#define CP_ASYNC16(dst_u32, src_ptr) \
    asm volatile("cp.async.ca.shared.global [%0], [%1], 16;" \
                 :: "r"(dst_u32), "l"(src_ptr) : "memory")
#define CP_COMMIT() asm volatile("cp.async.commit_group;" ::: "memory")
#define CP_WAIT1()  asm volatile("cp.async.wait_group 1;" ::: "memory")
#define CP_WAIT0()  asm volatile("cp.async.wait_group 0;" ::: "memory")

#define LDSM4(r, addr) \
    asm volatile("ldmatrix.sync.aligned.m8n8.x4.shared.b16 {%0,%1,%2,%3}, [%4];" \
                 : "=r"((r)[0]), "=r"((r)[1]), "=r"((r)[2]), "=r"((r)[3]) \
                 : "r"(addr))

// d += a*b (accumulate in place)
#define MMA16816(d, a, b0, b1) \
    asm volatile("mma.sync.aligned.m16n8k16.row.col.f32.f16.f16.f32 " \
                 "{%0,%1,%2,%3}, {%4,%5,%6,%7}, {%8,%9}, {%0,%1,%2,%3};" \
                 : "+f"((d)[0]), "+f"((d)[1]), "+f"((d)[2]), "+f"((d)[3]) \
                 : "r"((a)[0]), "r"((a)[1]), "r"((a)[2]), "r"((a)[3]), \
                   "r"(b0), "r"(b1))

// d = a*b + 0 (fresh partial; C = zero regs -> no explicit zeroing MOVs)
#define MMA16816_Z(d, a, b0, b1) \
    asm volatile("mma.sync.aligned.m16n8k16.row.col.f32.f16.f16.f32 " \
                 "{%0,%1,%2,%3}, {%4,%5,%6,%7}, {%8,%9}, {%10,%11,%12,%13};" \
                 : "=f"((d)[0]), "=f"((d)[1]), "=f"((d)[2]), "=f"((d)[3]) \
                 : "r"((a)[0]), "r"((a)[1]), "r"((a)[2]), "r"((a)[3]), \
                   "r"(b0), "r"(b1), \
                   "f"(0.0f), "f"(0.0f), "f"(0.0f), "f"(0.0f))

// ---------------------------------------------------------------------------
// Prep: split fp32 -> (fp16 hi, fp16 lo), optional scale, zero-pad K.
// ---------------------------------------------------------------------------
__device__ __forceinline__ void split4h(float4 v, float sc, ushort4& h, ushort4& l) {
    float a0 = v.x * sc, a1 = v.y * sc, a2 = v.z * sc, a3 = v.w * sc;
    __half h0 = __float2half_rn(a0);
    __half h1 = __float2half_rn(a1);
    __half h2 = __float2half_rn(a2);
    __half h3 = __float2half_rn(a3);
    __half l0 = __float2half_rn(a0 - __half2float(h0));
    __half l1 = __float2half_rn(a1 - __half2float(h1));
    __half l2 = __float2half_rn(a2 - __half2float(h2));
    __half l3 = __float2half_rn(a3 - __half2float(h3));
    h = make_ushort4(__half_as_ushort(h0), __half_as_ushort(h1),
                     __half_as_ushort(h2), __half_as_ushort(h3));
    l = make_ushort4(__half_as_ushort(l0), __half_as_ushort(l1),
                     __half_as_ushort(l2), __half_as_ushort(l3));
}

__global__ void k_split_x(const float* __restrict__ x) {
    int u = blockIdx.x * 256 + threadIdx.x;
    if (u >= M_TOT * 176) return;
    int m = u / 176, c = u - m * 176;
    float4 v = make_float4(0.f, 0.f, 0.f, 0.f);
    if (c < 175) v = *reinterpret_cast<const float4*>(x + (size_t)m * D0 + c * 4);
    ushort4 h, l;
    split4h(v, 1.0f, h, l);
    size_t o = (size_t)m * K_PAD + c * 4;
    *reinterpret_cast<ushort4*>(reinterpret_cast<unsigned short*>(g_xh) + o) = h;
    *reinterpret_cast<ushort4*>(reinterpret_cast<unsigned short*>(g_xl) + o) = l;
}

__global__ void k_split_w(const float* __restrict__ W1) {
    int u = blockIdx.x * 256 + threadIdx.x;
    if (u >= D1 * 176) return;
    int n = u / 176, c = u - n * 176;
    float4 v = make_float4(0.f, 0.f, 0.f, 0.f);
    if (c < 175) v = *reinterpret_cast<const float4*>(W1 + (size_t)n * D0 + c * 4);
    ushort4 h, l;
    split4h(v, W_SCALE, h, l);   // scale keeps wl out of fp16 subnormals
    size_t o = (size_t)n * K_PAD + c * 4;
    *reinterpret_cast<ushort4*>(reinterpret_cast<unsigned short*>(g_wh) + o) = h;
    *reinterpret_cast<ushort4*>(reinterpret_cast<unsigned short*>(g_wl) + o) = l;
}

// W2 [20,512] -> (16*W2) hi/lo fp16, padded to 32 rows (zeros).
__global__ void k_split_w2(const float* __restrict__ W2) {
    int u = blockIdx.x * 256 + threadIdx.x;          // one per 4 elems
    if (u >= D2P * D1 / 4) return;
    int n = u / (D1 / 4), c = u - n * (D1 / 4);
    float4 v = make_float4(0.f, 0.f, 0.f, 0.f);
    if (n < D2) v = *reinterpret_cast<const float4*>(W2 + (size_t)n * D1 + c * 4);
    ushort4 h, l;
    split4h(v, W_SCALE, h, l);
    size_t o = (size_t)n * D1 + c * 4;
    *reinterpret_cast<ushort4*>(reinterpret_cast<unsigned short*>(g_w2h) + o) = h;
    *reinterpret_cast<ushort4*>(reinterpret_cast<unsigned short*>(g_w2l) + o) = l;
}

// ---------------------------------------------------------------------------
// GEMM1: mma.sync fp16 3-split, per-k16 drained partials.
//   pre1*16 = x @ (16*W1)^T.  CTA tile 128x128, BK=16, 256 thr, 2x4 warps
//   (warp tile 64x32), double-buffered cp.async, 2 CTAs/SM.
//   ROW_B=48: 16B-aligned (cp.async/ldmatrix requirement) AND the 8-row
//   ldmatrix footprint covers all eight 16B banks mod 128 -> conflict-free.
// ---------------------------------------------------------------------------
#define BK       16
#define N_STAGES (K_PAD / BK)      // 44
#define ROW_B    48                // bytes per smem row (32B data + 16B pad)
#define TILEB    (128 * ROW_B)     // 6144 per tile
#define AH_T     0
#define AL_T     TILEB
#define BH_T     (2 * TILEB)
#define BL_T     (3 * TILEB)
#define STAGEB   (4 * TILEB)       // 24576
#define G1_SMEM  (2 * STAGEB)      // 49152

__global__ __launch_bounds__(256, 2)
void k_gemm1() {
    extern __shared__ char smem[];
    const uint32_t sb = smem_to_u32(smem);
    const int tid  = threadIdx.x;
    const int lane = tid & 31;
    const int wid  = tid >> 5;
    const int wm   = wid >> 2;      // 0..1 (M, 64-row warp tile)
    const int wn   = wid & 3;       // 0..3 (N, 32-col warp tile)

    const int m0 = blockIdx.y * 128;
    const int n0 = blockIdx.x * 128;

    // cp.async mapping: 128 rows x 2 16B-chunks = 256 units -> 1/thread/tile
    const int r = tid >> 1;         // 0..127
    const int q = tid & 1;          // 0..1
    const __half* srcA_h = g_xh + (size_t)(m0 + r) * K_PAD + q * 8;
    const __half* srcA_l = g_xl + (size_t)(m0 + r) * K_PAD + q * 8;
    const __half* srcB_h = g_wh + (size_t)(n0 + r) * K_PAD + q * 8;
    const __half* srcB_l = g_wl + (size_t)(n0 + r) * K_PAD + q * 8;
    const uint32_t dst_rq = (uint32_t)(r * ROW_B + q * 16);

    // ldmatrix lane addressing
    const int a_row  = lane & 15;
    const int a_cb   = (lane >> 4) * 16;
    const int b_row  = (lane & 7) + ((lane >> 4) & 1) * 8;
    const int b_cb   = ((lane >> 3) & 1) * 16;
    uint32_t aOff[4], bOff[2];
    #pragma unroll
    for (int i = 0; i < 4; i++)
        aOff[i] = (uint32_t)((wm * 64 + i * 16 + a_row) * ROW_B + a_cb);
    #pragma unroll
    for (int jp = 0; jp < 2; jp++)
        bOff[jp] = (uint32_t)((wn * 32 + jp * 16 + b_row) * ROW_B + b_cb);

    float tot[4][4][4] = {};   // [m-frag][n8-frag][reg]

    {   // prologue: stage 0
        uint32_t d = sb + dst_rq;
        CP_ASYNC16(d + AH_T, srcA_h);
        CP_ASYNC16(d + AL_T, srcA_l);
        CP_ASYNC16(d + BH_T, srcB_h);
        CP_ASYNC16(d + BL_T, srcB_l);
        CP_COMMIT();
    }

    for (int s = 0; s < N_STAGES; s++) {
        if (s + 1 < N_STAGES) {
            size_t ko = (size_t)(s + 1) * BK;
            uint32_t d = sb + ((s + 1) & 1) * STAGEB + dst_rq;
            CP_ASYNC16(d + AH_T, srcA_h + ko);
            CP_ASYNC16(d + AL_T, srcA_l + ko);
            CP_ASYNC16(d + BH_T, srcB_h + ko);
            CP_ASYNC16(d + BL_T, srcB_l + ko);
            CP_COMMIT();
            CP_WAIT1();
        } else {
            CP_WAIT0();
        }
        __syncthreads();

        const uint32_t base = sb + (s & 1) * STAGEB;

        uint32_t bh[2][4], bl[2][4];
        #pragma unroll
        for (int jp = 0; jp < 2; jp++) {
            LDSM4(bh[jp], base + BH_T + bOff[jp]);
            LDSM4(bl[jp], base + BL_T + bOff[jp]);
        }

        #pragma unroll
        for (int i = 0; i < 4; i++) {
            uint32_t ah[4], al[4];
            LDSM4(ah, base + AH_T + aOff[i]);
            LDSM4(al, base + AL_T + aOff[i]);
            #pragma unroll
            for (int j = 0; j < 4; j++) {
                const int jp = j >> 1, e = (j & 1) * 2;
                float P[4];
                MMA16816_Z(P, ah, bh[jp][e], bh[jp][e + 1]);
                MMA16816(P, ah, bl[jp][e], bl[jp][e + 1]);
                MMA16816(P, al, bh[jp][e], bh[jp][e + 1]);
                tot[i][j][0] += P[0];
                tot[i][j][1] += P[1];
                tot[i][j][2] += P[2];
                tot[i][j][3] += P[3];
            }
        }
        __syncthreads();
    }

    // epilogue
    const int g  = lane >> 2;
    const int tg = lane & 3;
    #pragma unroll
    for (int i = 0; i < 4; i++) {
        const int m = m0 + wm * 64 + i * 16 + g;
        #pragma unroll
        for (int j = 0; j < 4; j++) {
            const int n = n0 + wn * 32 + j * 8 + tg * 2;
            *reinterpret_cast<float2*>(g_pre1 + (size_t)m * D1 + n) =
                make_float2(tot[i][j][0], tot[i][j][1]);
            *reinterpret_cast<float2*>(g_pre1 + (size_t)(m + 8) * D1 + n) =
                make_float2(tot[i][j][2], tot[i][j][3]);
        }
    }
}

// ---------------------------------------------------------------------------
// Layer-1 LIF scan. Writes fp32 s1 (output) and fp16 s1h (gemm2 input).
// ---------------------------------------------------------------------------
__global__ void k_scan1(float* __restrict__ s1) {
    int idx = blockIdx.x * blockDim.x + threadIdx.x;
    if (idx >= BATCH * D1) return;

    float syn = 0.0f, mem = 0.0f;
    const float* p = g_pre1 + idx;
    float* s = s1 + idx;
    __half* sh = g_s1h + idx;

    #pragma unroll 4
    for (int t = 0; t < T_STEPS; t++) {
        float pr = p[(size_t)t * (BATCH * D1)] * INV_W_SCALE;
        syn = ALPHA * syn + pr;
        float reset = (mem > THR) ? 1.0f : 0.0f;
        mem = (BETA * mem + syn) * (1.0f - reset);
        float sp = (mem > THR) ? 1.0f : 0.0f;
        s[(size_t)t * (BATCH * D1)] = sp;
        sh[(size_t)t * (BATCH * D1)] = __float2half_rn(sp);   // exact (0 or 1)
    }
}

// ---------------------------------------------------------------------------
// GEMM2 via mma.sync: pre2*16 = s1h @ (16*W2)^T   (M=51200, K=512, N=32 pad)
//   Block = 128 thr (4 warps) x 64 rows.  K chunks of 128, single buffer.
// ---------------------------------------------------------------------------
#define G2_ROW_B 272                       // 128 halfs = 256 B, pad to 272
#define G2_A     0
#define G2_BH    (64 * G2_ROW_B)           // 17408
#define G2_BL    (G2_BH + 32 * G2_ROW_B)   // 26112
#define G2_SMEM  (G2_BL + 32 * G2_ROW_B)   // 34816

__global__ __launch_bounds__(128)
void k_gemm2() {
    __shared__ char smem[G2_SMEM];
    const uint32_t sb = smem_to_u32(smem);
    const int tid  = threadIdx.x;
    const int lane = tid & 31;
    const int wid  = tid >> 5;
    const int m0   = blockIdx.x * 64;

    const int a_row = lane & 15;
    const int a_cb  = (lane >> 4) * 16;
    const int b_row = (lane & 7) + ((lane >> 4) & 1) * 8;
    const int b_cb  = ((lane >> 3) & 1) * 16;
    const uint32_t aOff = (uint32_t)((wid * 16 + a_row) * G2_ROW_B + a_cb);
    uint32_t bOff[2];
    #pragma unroll
    for (int jp = 0; jp < 2; jp++)
        bOff[jp] = (uint32_t)((jp * 16 + b_row) * G2_ROW_B + b_cb);

    float tot[4][4] = {};

    for (int kc = 0; kc < 4; kc++) {
        const int k0 = kc * 128;
        // A: 64 rows x 16 16B-chunks = 1024 units -> 8/thread
        #pragma unroll
        for (int i = 0; i < 8; i++) {
            int u = tid + i * 128;
            int rr = u >> 4, qq = u & 15;
            CP_ASYNC16(sb + G2_A + rr * G2_ROW_B + qq * 16,
                       g_s1h + (size_t)(m0 + rr) * D1 + k0 + qq * 8);
        }
        // Bh/Bl: 32 rows x 16 chunks = 512 units -> 4/thread each
        #pragma unroll
        for (int i = 0; i < 4; i++) {
            int u = tid + i * 128;
            int rr = u >> 4, qq = u & 15;
            CP_ASYNC16(sb + G2_BH + rr * G2_ROW_B + qq * 16,
                       g_w2h + (size_t)rr * D1 + k0 + qq * 8);
            CP_ASYNC16(sb + G2_BL + rr * G2_ROW_B + qq * 16,
                       g_w2l + (size_t)rr * D1 + k0 + qq * 8);
        }
        CP_COMMIT();
        CP_WAIT0();
        __syncthreads();

        float Pc[4][4];
        #pragma unroll
        for (int ks = 0; ks < 8; ks++) {
            const uint32_t kb = ks * 32;
            uint32_t af[4], bhf[2][4], blf[2][4];
            LDSM4(af, sb + G2_A + aOff + kb);
            #pragma unroll
            for (int jp = 0; jp < 2; jp++) {
                LDSM4(bhf[jp], sb + G2_BH + bOff[jp] + kb);
                LDSM4(blf[jp], sb + G2_BL + bOff[jp] + kb);
            }
            #pragma unroll
            for (int j = 0; j < 4; j++) {
                const int jp = j >> 1, e = (j & 1) * 2;
                if (ks == 0) {
                    MMA16816_Z(Pc[j], af, bhf[jp][e], bhf[jp][e + 1]);
                } else {
                    MMA16816(Pc[j], af, bhf[jp][e], bhf[jp][e + 1]);
                }
                MMA16816(Pc[j], af, blf[jp][e], blf[jp][e + 1]);
            }
        }
        #pragma unroll
        for (int j = 0; j < 4; j++)
            #pragma unroll
            for (int e = 0; e < 4; e++) tot[j][e] += Pc[j][e];
        __syncthreads();
    }

    // epilogue: write n < 20 only
    const int g  = lane >> 2;
    const int tg = lane & 3;
    const int m  = m0 + wid * 16 + g;
    #pragma unroll
    for (int j = 0; j < 3; j++) {          // j=3 -> n>=24, all padded
        const int n = j * 8 + tg * 2;
        if (n + 1 < D2) {
            *reinterpret_cast<float2*>(g_pre2 + (size_t)m * D2 + n) =
                make_float2(tot[j][0], tot[j][1]);
            *reinterpret_cast<float2*>(g_pre2 + (size_t)(m + 8) * D2 + n) =
                make_float2(tot[j][2], tot[j][3]);
        }
    }
}

// ---------------------------------------------------------------------------
// Layer-2 LIF scan (pre2 carries 16x scale; undo exactly).
// ---------------------------------------------------------------------------
__global__ void k_scan2(float* __restrict__ out0, float* __restrict__ out2) {
    int idx = blockIdx.x * blockDim.x + threadIdx.x;
    if (idx >= BATCH * D2) return;

    float syn = 0.0f, mem = 0.0f;
    const float* p = g_pre2 + idx;

    #pragma unroll 4
    for (int t = 0; t < T_STEPS; t++) {
        float pr = p[(size_t)t * (BATCH * D2)] * INV_W_SCALE;
        syn = ALPHA * syn + pr;
        float reset = (mem > THR) ? 1.0f : 0.0f;
        mem = (BETA * mem + syn) * (1.0f - reset);
        float sp = (mem > THR) ? 1.0f : 0.0f;
        out0[(size_t)t * (BATCH * D2) + idx] = sp;
        out2[(size_t)t * (BATCH * D2) + idx] = sp;
    }
}

// ---------------------------------------------------------------------------
// Launch
// ---------------------------------------------------------------------------
extern "C" void kernel_launch(void* const* d_in, const int* in_sizes, int n_in,
                              void* d_out, int out_size) {
    const float* x  = (const float*)d_in[0];   // [100, 512, 700]
    const float* W1 = (const float*)d_in[1];   // [512, 700]
    const float* W2 = (const float*)d_in[2];   // [20, 512]

    float* out  = (float*)d_out;
    float* out0 = out;                          // s2, copy 1
    float* s1   = out + S2_ELEMS;               // s1
    float* out2 = out + S2_ELEMS + S1_ELEMS;    // s2, copy 2

    cudaFuncSetAttribute(k_gemm1, cudaFuncAttributeMaxDynamicSharedMemorySize, G1_SMEM);

    // 0) splits
    k_split_x<<<(M_TOT * 176 + 255) / 256, 256>>>(x);
    k_split_w<<<(D1 * 176 + 255) / 256, 256>>>(W1);
    k_split_w2<<<(D2P * D1 / 4 + 255) / 256, 256>>>(W2);

    // 1) pre1*16 = x @ (16*W1)^T  (256 thr, 2 CTAs/SM)
    dim3 g1(D1 / 128, M_TOT / 128);             // (4, 400)
    k_gemm1<<<g1, 256, G1_SMEM>>>();

    // 2) layer-1 scan -> s1 (fp32) + s1h (fp16)
    k_scan1<<<(BATCH * D1 + 255) / 256, 256>>>(s1);

    // 3) pre2*16 = s1h @ (16*W2)^T via mma.sync
    k_gemm2<<<M_TOT / 64, 128>>>();

    // 4) layer-2 scan -> s2 (both copies)
    k_scan2<<<(BATCH * D2 + 255) / 256, 256>>>(out0, out2);
}